// round 13
// baseline (speedup 1.0000x reference)
#include <cuda_runtime.h>
#include <cuda_bf16.h>
#include <cstdint>

#define V     2048
#define DIN   64
#define DOUT  64
#define NB    64            // A*B = 8*8
#define NCOL  (NB * DOUT)   // 4096 columns of the big GEMM

// ---------------- scratch (device globals; no cudaMalloc allowed) ----------
__device__ __nv_bfloat16 g_adjT[(size_t)V * V];   // 8 MB: adjT[j][v] = bf16(adj[v][j]*rinv[v])
__device__ __nv_bfloat16 g_xT[(size_t)NCOL * V];  // 16 MB: xT[c][v] = bf16((x@W)[ab,v,d])
__device__ float g_part[32][V];                   // colsum partials (overwritten fully each run)
__device__ float g_rinv[V];

// ---------------- helpers ---------------------------------------------------
__device__ __forceinline__ uint32_t smem_u32(const void* p) {
    uint32_t a;
    asm("{ .reg .u64 t; cvta.to.shared.u64 t, %1; cvt.u32.u64 %0, t; }" : "=r"(a) : "l"(p));
    return a;
}
#define CP_ASYNC16(dst, src) \
    asm volatile("cp.async.cg.shared.global [%0], [%1], 16;" :: "r"(dst), "l"(src) : "memory")
#define CP_COMMIT() asm volatile("cp.async.commit_group;" ::: "memory")
#define CP_WAIT(n)  asm volatile("cp.async.wait_group %0;" :: "n"(n) : "memory")

// m16n8k16 bf16 mma: D += A*B, fp32 accum
__device__ __forceinline__ void mma_bf16(float* d, const uint32_t* a, const uint32_t* b) {
    asm volatile(
        "mma.sync.aligned.m16n8k16.row.col.f32.bf16.bf16.f32 "
        "{%0,%1,%2,%3}, {%4,%5,%6,%7}, {%8,%9}, {%0,%1,%2,%3};"
        : "+f"(d[0]), "+f"(d[1]), "+f"(d[2]), "+f"(d[3])
        : "r"(a[0]), "r"(a[1]), "r"(a[2]), "r"(a[3]), "r"(b[0]), "r"(b[1]));
}
#define LDMATRIX_X4(r0, r1, r2, r3, addr) \
    asm volatile("ldmatrix.sync.aligned.m8n8.x4.shared.b16 {%0,%1,%2,%3}, [%4];" \
        : "=r"(r0), "=r"(r1), "=r"(r2), "=r"(r3) : "r"(addr))

// ---------------------------------------------------------------------------
// Fused launch 1: blocks [0,1024) = project, blocks [1024,1280) = colsum.
// Independent: colsum writes g_part; project writes g_xT.
// Occupancy-tuned: b-frags loaded inside a ROLLED k16 loop (16 live regs,
// not 64), __launch_bounds__(256,6) caps regs at ~42 -> 6 blocks/SM.
// ---------------------------------------------------------------------------
#define PJ_WTST  72                  // Wth row stride (halves)
#define PJ_XST   72                  // Xs row stride (halves)
#define PJ_YST   136                 // Ys row stride (halves)
#define PJ_WT_BYTES (DOUT * PJ_WTST * 2)       // 9216
#define PJ_XS_BYTES (128 * PJ_XST * 2)         // 18432 (Ys needs 64*136*2=17408 <=)

__global__ void __launch_bounds__(256, 6) fused_proj_colsum_kernel(
        const float* __restrict__ x, const float* __restrict__ w,
        const float* __restrict__ adj) {
    __shared__ __align__(16) char smem_raw[PJ_WT_BYTES + PJ_XS_BYTES];

    int tid = threadIdx.x;
    int b   = blockIdx.x;

    if (b >= 1024) {
        // ---- colsum partials: g_part[ib][j] = sum of 64 adj rows ----
        // two independent accumulators -> MLP 16
        int cb = b - 1024;
        int j  = (cb & 7) * 256 + tid;
        int i0 = (cb >> 3) * 64;
        float s0 = 0.0f, s1 = 0.0f;
#pragma unroll 8
        for (int i = 0; i < 32; i++) {
            s0 += adj[(size_t)(i0 + 2 * i)     * V + j];
            s1 += adj[(size_t)(i0 + 2 * i + 1) * V + j];
        }
        g_part[cb >> 3][j] = s0 + s1;
        return;
    }

    // ---- project ----
    __nv_bfloat16* Wth = (__nv_bfloat16*)smem_raw;                  // [d][k]
    __nv_bfloat16* Xs  = (__nv_bfloat16*)(smem_raw + PJ_WT_BYTES);  // [v][k]
    __nv_bfloat16* Ys  = Xs;                                        // reused

    int wid  = tid >> 5, lane = tid & 31;
    int lg   = lane >> 2, lc = lane & 3;
    int ab   = b >> 4;
    int v0   = (b & 15) * 128;

    // stage W transposed to bf16: Wth[d][k] = bf16(w[k][d])
#pragma unroll
    for (int s = tid; s < 1024; s += 256) {
        int k = s >> 4, dq = (s & 15) * 4;
        float4 f = *(const float4*)&w[k * DOUT + dq];
        Wth[(dq + 0) * PJ_WTST + k] = __float2bfloat16_rn(f.x);
        Wth[(dq + 1) * PJ_WTST + k] = __float2bfloat16_rn(f.y);
        Wth[(dq + 2) * PJ_WTST + k] = __float2bfloat16_rn(f.z);
        Wth[(dq + 3) * PJ_WTST + k] = __float2bfloat16_rn(f.w);
    }
    // stage x rows v0..v0+127 -> bf16 Xs
    {
        const float* xb = x + ((size_t)ab * V + v0) * DIN;
#pragma unroll
        for (int s = tid; s < 2048; s += 256) {
            int r = s >> 4, kq = s & 15;
            float4 f = *(const float4*)&xb[(size_t)r * DIN + kq * 4];
            __nv_bfloat162 h0 = __floats2bfloat162_rn(f.x, f.y);
            __nv_bfloat162 h1 = __floats2bfloat162_rn(f.z, f.w);
            *(uint2*)&Xs[r * PJ_XST + kq * 4] = make_uint2(*(uint32_t*)&h0, *(uint32_t*)&h1);
        }
    }
    __syncthreads();

    float d[8][4];
#pragma unroll
    for (int j = 0; j < 8; j++)
#pragma unroll
        for (int q = 0; q < 4; q++) d[j][q] = 0.0f;

    uint32_t xs_base = smem_u32(Xs);
    int r_a = lane & 15, ka = (lane >> 4) * 8;
    uint32_t a_addr0 = xs_base + (uint32_t)((wid * 16 + r_a) * PJ_XST + ka) * 2u;
    int k0b = lc * 2;   // b-frag k base within k16

    // ROLLED k16 loop: b-frags loaded per iteration (16 live regs, not 64)
#pragma unroll 1
    for (int k16 = 0; k16 < 4; k16++) {
        uint32_t a[4];
        LDMATRIX_X4(a[0], a[1], a[2], a[3], a_addr0 + (uint32_t)(k16 * 16 * 2));
#pragma unroll
        for (int fj = 0; fj < 8; fj++) {
            int n  = fj * 8 + lg;
            int kk = k16 * 16 + k0b;
            uint32_t bf0 = *(const uint32_t*)&Wth[n * PJ_WTST + kk];
            uint32_t bf1 = *(const uint32_t*)&Wth[n * PJ_WTST + kk + 8];
            uint32_t bfr[2] = {bf0, bf1};
            mma_bf16(d[fj], a, bfr);
        }
    }
    __syncthreads();   // all Xs reads done; reuse as Ys

#pragma unroll
    for (int fj = 0; fj < 8; fj++) {
        int n    = fj * 8 + lc * 2;
        int vlo  = wid * 16 + lg;
        int vhi  = vlo + 8;
        Ys[n * PJ_YST + vlo]       = __float2bfloat16_rn(d[fj][0]);
        Ys[(n + 1) * PJ_YST + vlo] = __float2bfloat16_rn(d[fj][1]);
        Ys[n * PJ_YST + vhi]       = __float2bfloat16_rn(d[fj][2]);
        Ys[(n + 1) * PJ_YST + vhi] = __float2bfloat16_rn(d[fj][3]);
    }
    __syncthreads();

#pragma unroll
    for (int s = tid; s < 1024; s += 256) {
        int n = s >> 4, vq = s & 15;
        uint4 val = *(uint4*)&Ys[n * PJ_YST + vq * 8];
        *(uint4*)&g_xT[(size_t)(ab * 64 + n) * V + v0 + vq * 8] = val;
    }
}

// ---------------------------------------------------------------------------
// transpose (+inline rinv): adjT[j][v] = bf16(adj[v][j] * rinv[v])
//   rinv reduced per block from g_part (same order as before — bitwise
//   identical); blocks with blockIdx.x==0 publish g_rinv for agg epilogue.
// ---------------------------------------------------------------------------
__global__ void __launch_bounds__(256) transpose_kernel(const float* __restrict__ adj) {
    __shared__ float ts[64][65];   // ts[j][v]
    __shared__ float rs[64];
    int tid = threadIdx.x;
    int j0 = blockIdx.x * 64, v0 = blockIdx.y * 64;

#pragma unroll
    for (int p = 0; p < 4; p++) {
        int r = p * 16 + (tid >> 4);
        int c = (tid & 15) * 4;
        float4 f = *(const float4*)&adj[(size_t)(v0 + r) * V + j0 + c];
        ts[c + 0][r] = f.x;
        ts[c + 1][r] = f.y;
        ts[c + 2][r] = f.z;
        ts[c + 3][r] = f.w;
    }
    if (tid < 64) {
        float s = 0.0f;
#pragma unroll
        for (int i = 0; i < 32; i++) s += g_part[i][v0 + tid];
        float r = rsqrtf(s);
        rs[tid] = r;
        if (blockIdx.x == 0) g_rinv[v0 + tid] = r;
    }
    __syncthreads();

#pragma unroll
    for (int p = 0; p < 2; p++) {
        int jr = p * 32 + (tid >> 3);
        int vo = (tid & 7) * 8;
        __nv_bfloat16 h[8];
#pragma unroll
        for (int i = 0; i < 8; i++)
            h[i] = __float2bfloat16_rn(ts[jr][vo + i] * rs[vo + i]);
        *(uint4*)&g_adjT[(size_t)(j0 + jr) * V + v0 + vo] = *(uint4*)h;
    }
}

// ---------------------------------------------------------------------------
// agg: mma.sync bf16 GEMM, CTA 128x128, 8 warps (warp 64x32), OCCUPANCY 2
// KC=64, 3-stage cp.async pipeline, one __syncthreads per chunk
// ---------------------------------------------------------------------------
#define MT 128
#define NT 128
#define KC 64
#define NCHUNK (V / KC)               // 32
#define LDS_STRIDE 72                 // halves per row (144 B, ldmatrix bank-free)
#define A_HALVES (MT * LDS_STRIDE)    // 9216
#define B_HALVES (NT * LDS_STRIDE)    // 9216
#define ST_HALVES (A_HALVES + B_HALVES)
#define SM_BYTES (3 * ST_HALVES * 2)  // 110592 B -> 2 CTAs/SM = 216 KB

__device__ __forceinline__ void load_chunk(uint32_t smem_base, int stage,
                                           int j0, int n0, int k0, int tid) {
    uint32_t sa = smem_base + (uint32_t)stage * ((uint32_t)ST_HALVES * 2u);
    uint32_t sb = sa + (uint32_t)A_HALVES * 2u;
#pragma unroll
    for (int q = 0; q < 4; q++) {
        int s = tid + q * 256;
        int r = s >> 3, o = s & 7;
        uint32_t dst = sa + (uint32_t)(r * LDS_STRIDE + o * 8) * 2u;
        CP_ASYNC16(dst, &g_adjT[(size_t)(j0 + r) * V + k0 + o * 8]);
    }
#pragma unroll
    for (int q = 0; q < 4; q++) {
        int s = tid + q * 256;
        int r = s >> 3, o = s & 7;
        uint32_t dst = sb + (uint32_t)(r * LDS_STRIDE + o * 8) * 2u;
        CP_ASYNC16(dst, &g_xT[(size_t)(n0 + r) * V + k0 + o * 8]);
    }
}

__global__ void __launch_bounds__(256, 2) agg_mma_kernel(const float* __restrict__ bias,
                                                         float* __restrict__ out) {
    extern __shared__ __align__(16) __nv_bfloat16 smem[];
    uint32_t smem_base = smem_u32(smem);
    int tid  = threadIdx.x;
    int wid  = tid >> 5, lane = tid & 31;
    int j0   = blockIdx.x * MT;
    int n0   = blockIdx.y * NT;
    int m0w  = (wid & 1) * 64;
    int n0w  = (wid >> 1) * 32;
    int lg   = lane >> 2, lc = lane & 3;

    int r_a   = lane & 15;
    int ka    = (lane >> 4) * 8;
    int n_off = (lane & 7) + ((lane >> 4) & 1) * 8;
    int k_off = ((lane >> 3) & 1) * 8;

    float d[4][4][4];
#pragma unroll
    for (int i = 0; i < 4; i++)
#pragma unroll
        for (int j = 0; j < 4; j++)
#pragma unroll
            for (int q = 0; q < 4; q++) d[i][j][q] = 0.0f;

    load_chunk(smem_base, 0, j0, n0, 0, tid);   CP_COMMIT();
    load_chunk(smem_base, 1, j0, n0, KC, tid);  CP_COMMIT();

    for (int i = 0; i < NCHUNK; i++) {
        if (i < NCHUNK - 1) { CP_WAIT(1); } else { CP_WAIT(0); }
        __syncthreads();   // chunk i resident; releases stage (i-1)%3

        int stage = i % 3;
        uint32_t As = smem_base + (uint32_t)stage * ((uint32_t)ST_HALVES * 2u);
        uint32_t Bs = As + (uint32_t)A_HALVES * 2u;
        uint32_t a_base = As + (uint32_t)((m0w + r_a) * LDS_STRIDE + ka) * 2u;
        uint32_t b_base = Bs + (uint32_t)((n0w + n_off) * LDS_STRIDE + k_off) * 2u;

#pragma unroll
        for (int k16 = 0; k16 < 4; k16++) {
            uint32_t kb2 = (uint32_t)(k16 * 16 * 2);
            uint32_t a[4][4], b[4][2];
#pragma unroll
            for (int fi = 0; fi < 4; fi++) {
                LDMATRIX_X4(a[fi][0], a[fi][1], a[fi][2], a[fi][3],
                            a_base + (uint32_t)(fi * 16 * LDS_STRIDE * 2) + kb2);
            }
#pragma unroll
            for (int p = 0; p < 2; p++) {
                LDMATRIX_X4(b[2 * p][0], b[2 * p][1], b[2 * p + 1][0], b[2 * p + 1][1],
                            b_base + (uint32_t)(p * 16 * LDS_STRIDE * 2) + kb2);
            }
#pragma unroll
            for (int fi = 0; fi < 4; fi++)
#pragma unroll
                for (int fj = 0; fj < 4; fj++)
                    mma_bf16(d[fi][fj], a[fi], b[fj]);
        }
        if (i + 2 < NCHUNK) {
            load_chunk(smem_base, (i + 2) % 3, j0, n0, (i + 2) * KC, tid);
            CP_COMMIT();
        }
    }

    // epilogue
#pragma unroll
    for (int fi = 0; fi < 4; fi++) {
        int row_lo = j0 + m0w + fi * 16 + lg;
        int row_hi = row_lo + 8;
        float rlo = g_rinv[row_lo];
        float rhi = g_rinv[row_hi];
#pragma unroll
        for (int fj = 0; fj < 4; fj++) {
            int c  = n0 + n0w + fj * 8 + lc * 2;
            int ab = c >> 6;
            int dd = c & 63;
            float2 bi = *(const float2*)&bias[dd];
            float2 olo, ohi;
            olo.x = fmaxf(bi.x + rlo * d[fi][fj][0], 0.0f);
            olo.y = fmaxf(bi.y + rlo * d[fi][fj][1], 0.0f);
            ohi.x = fmaxf(bi.x + rhi * d[fi][fj][2], 0.0f);
            ohi.y = fmaxf(bi.y + rhi * d[fi][fj][3], 0.0f);
            *(float2*)&out[((size_t)ab * V + row_lo) * DOUT + dd] = olo;
            *(float2*)&out[((size_t)ab * V + row_hi) * DOUT + dd] = ohi;
        }
    }
}

// ---------------------------------------------------------------------------
extern "C" void kernel_launch(void* const* d_in, const int* in_sizes, int n_in,
                              void* d_out, int out_size) {
    const float* adj  = (const float*)d_in[0];
    const float* x    = (const float*)d_in[1];
    const float* w    = (const float*)d_in[2];
    const float* bias = (const float*)d_in[3];
    float* out        = (float*)d_out;

    cudaFuncSetAttribute(agg_mma_kernel, cudaFuncAttributeMaxDynamicSharedMemorySize, SM_BYTES);

    fused_proj_colsum_kernel<<<1280, 256>>>(x, w, adj);
    transpose_kernel<<<dim3(32, 32), 256>>>(adj);
    agg_mma_kernel<<<dim3(V / MT, NCOL / NT), 256, SM_BYTES>>>(bias, out);
}

// round 14
// speedup vs baseline: 1.0132x; 1.0132x over previous
#include <cuda_runtime.h>
#include <cuda_bf16.h>
#include <cstdint>

#define V     2048
#define DIN   64
#define DOUT  64
#define NB    64            // A*B = 8*8
#define NCOL  (NB * DOUT)   // 4096 columns of the big GEMM

// ---------------- scratch (device globals; no cudaMalloc allowed) ----------
__device__ __nv_bfloat16 g_adjT[(size_t)V * V];   // 8 MB: adjT[j][v] = bf16(adj[v][j]*rinv[v])
__device__ __nv_bfloat16 g_xT[(size_t)NCOL * V];  // 16 MB: xT[c][v] = bf16((x@W)[ab,v,d])
__device__ float g_part[32][V];                   // colsum partials (overwritten fully each run)
__device__ float g_rinv[V];

// ---------------- helpers ---------------------------------------------------
__device__ __forceinline__ uint32_t smem_u32(const void* p) {
    uint32_t a;
    asm("{ .reg .u64 t; cvta.to.shared.u64 t, %1; cvt.u32.u64 %0, t; }" : "=r"(a) : "l"(p));
    return a;
}
#define CP_ASYNC16(dst, src) \
    asm volatile("cp.async.cg.shared.global [%0], [%1], 16;" :: "r"(dst), "l"(src) : "memory")
#define CP_COMMIT() asm volatile("cp.async.commit_group;" ::: "memory")
#define CP_WAIT(n)  asm volatile("cp.async.wait_group %0;" :: "n"(n) : "memory")

// m16n8k16 bf16 mma: D += A*B, fp32 accum
__device__ __forceinline__ void mma_bf16(float* d, const uint32_t* a, const uint32_t* b) {
    asm volatile(
        "mma.sync.aligned.m16n8k16.row.col.f32.bf16.bf16.f32 "
        "{%0,%1,%2,%3}, {%4,%5,%6,%7}, {%8,%9}, {%0,%1,%2,%3};"
        : "+f"(d[0]), "+f"(d[1]), "+f"(d[2]), "+f"(d[3])
        : "r"(a[0]), "r"(a[1]), "r"(a[2]), "r"(a[3]), "r"(b[0]), "r"(b[1]));
}
#define LDMATRIX_X4(r0, r1, r2, r3, addr) \
    asm volatile("ldmatrix.sync.aligned.m8n8.x4.shared.b16 {%0,%1,%2,%3}, [%4];" \
        : "=r"(r0), "=r"(r1), "=r"(r2), "=r"(r3) : "r"(addr))

// ---------------------------------------------------------------------------
// Fused launch 1 (SINGLE WAVE): blocks [0,256) = project (4 v-tiles each),
// blocks [256,512) = colsum. 512 blocks < 740 resident slots -> 1 wave.
// project body = R12 shape (prebuilt bfr, fully unrolled k16 — ptxas folds
// the b-frag LDS next to the mmas; measured 48 regs / occ 5).
// ---------------------------------------------------------------------------
#define PJ_WTST  72                  // Wth row stride (halves)
#define PJ_XST   72                  // Xs row stride (halves)
#define PJ_YST   136                 // Ys row stride (halves)
#define PJ_WT_BYTES (DOUT * PJ_WTST * 2)       // 9216
#define PJ_XS_BYTES (128 * PJ_XST * 2)         // 18432 (Ys needs 64*136*2=17408 <=)

__global__ void __launch_bounds__(256) fused_proj_colsum_kernel(
        const float* __restrict__ x, const float* __restrict__ w,
        const float* __restrict__ adj) {
    __shared__ __align__(16) char smem_raw[PJ_WT_BYTES + PJ_XS_BYTES];

    int tid = threadIdx.x;
    int b   = blockIdx.x;

    if (b >= 256) {
        // ---- colsum partials: g_part[ib][j] = sum of 64 adj rows ----
        int cb = b - 256;
        int j  = (cb & 7) * 256 + tid;
        int i0 = (cb >> 3) * 64;
        float s0 = 0.0f, s1 = 0.0f;
#pragma unroll 8
        for (int i = 0; i < 32; i++) {
            s0 += adj[(size_t)(i0 + 2 * i)     * V + j];
            s1 += adj[(size_t)(i0 + 2 * i + 1) * V + j];
        }
        g_part[cb >> 3][j] = s0 + s1;
        return;
    }

    // ---- project: 4 v-tiles of one ab per block ----
    __nv_bfloat16* Wth = (__nv_bfloat16*)smem_raw;                  // [d][k]
    __nv_bfloat16* Xs  = (__nv_bfloat16*)(smem_raw + PJ_WT_BYTES);  // [v][k]
    __nv_bfloat16* Ys  = Xs;                                        // reused per tile

    int wid  = tid >> 5, lane = tid & 31;
    int lg   = lane >> 2, lc = lane & 3;
    int ab   = b >> 2;
    int vt0  = (b & 3) * 4;          // first of 4 v-tiles

    // stage W transposed to bf16: Wth[d][k] = bf16(w[k][d])
#pragma unroll
    for (int s = tid; s < 1024; s += 256) {
        int k = s >> 4, dq = (s & 15) * 4;
        float4 f = *(const float4*)&w[k * DOUT + dq];
        Wth[(dq + 0) * PJ_WTST + k] = __float2bfloat16_rn(f.x);
        Wth[(dq + 1) * PJ_WTST + k] = __float2bfloat16_rn(f.y);
        Wth[(dq + 2) * PJ_WTST + k] = __float2bfloat16_rn(f.z);
        Wth[(dq + 3) * PJ_WTST + k] = __float2bfloat16_rn(f.w);
    }
    // stage x for tile 0
    {
        const float* xb = x + ((size_t)ab * V + vt0 * 128) * DIN;
#pragma unroll
        for (int s = tid; s < 2048; s += 256) {
            int r = s >> 4, kq = s & 15;
            float4 f = *(const float4*)&xb[(size_t)r * DIN + kq * 4];
            __nv_bfloat162 h0 = __floats2bfloat162_rn(f.x, f.y);
            __nv_bfloat162 h1 = __floats2bfloat162_rn(f.z, f.w);
            *(uint2*)&Xs[r * PJ_XST + kq * 4] = make_uint2(*(uint32_t*)&h0, *(uint32_t*)&h1);
        }
    }
    __syncthreads();

    // b-frags (R12 shape): ptxas folds these LDS next to the mmas
    uint32_t bfr[4][8][2];
#pragma unroll
    for (int k16 = 0; k16 < 4; k16++) {
#pragma unroll
        for (int fj = 0; fj < 8; fj++) {
            int n  = fj * 8 + lg;
            int k0 = k16 * 16 + lc * 2;
            bfr[k16][fj][0] = *(const uint32_t*)&Wth[n * PJ_WTST + k0];
            bfr[k16][fj][1] = *(const uint32_t*)&Wth[n * PJ_WTST + k0 + 8];
        }
    }

    uint32_t xs_base = smem_u32(Xs);
    int r_a = lane & 15, ka = (lane >> 4) * 8;
    uint32_t a_addr0 = xs_base + (uint32_t)((wid * 16 + r_a) * PJ_XST + ka) * 2u;

#pragma unroll 1
    for (int it = 0; it < 4; it++) {
        int v0 = (vt0 + it) * 128;

        float d[8][4];
#pragma unroll
        for (int j = 0; j < 8; j++)
#pragma unroll
            for (int q = 0; q < 4; q++) d[j][q] = 0.0f;

#pragma unroll
        for (int k16 = 0; k16 < 4; k16++) {
            uint32_t a[4];
            LDMATRIX_X4(a[0], a[1], a[2], a[3], a_addr0 + (uint32_t)(k16 * 16 * 2));
#pragma unroll
            for (int fj = 0; fj < 8; fj++) mma_bf16(d[fj], a, bfr[k16][fj]);
        }
        __syncthreads();   // all Xs reads done; reuse as Ys

#pragma unroll
        for (int fj = 0; fj < 8; fj++) {
            int n    = fj * 8 + lc * 2;
            int vlo  = wid * 16 + lg;
            int vhi  = vlo + 8;
            Ys[n * PJ_YST + vlo]       = __float2bfloat16_rn(d[fj][0]);
            Ys[(n + 1) * PJ_YST + vlo] = __float2bfloat16_rn(d[fj][1]);
            Ys[n * PJ_YST + vhi]       = __float2bfloat16_rn(d[fj][2]);
            Ys[(n + 1) * PJ_YST + vhi] = __float2bfloat16_rn(d[fj][3]);
        }
        __syncthreads();

#pragma unroll
        for (int s = tid; s < 1024; s += 256) {
            int n = s >> 4, vq = s & 15;
            uint4 val = *(uint4*)&Ys[n * PJ_YST + vq * 8];
            *(uint4*)&g_xT[(size_t)(ab * 64 + n) * V + v0 + vq * 8] = val;
        }

        if (it < 3) {
            __syncthreads();   // Ys reads done before restaging Xs
            const float* xb = x + ((size_t)ab * V + (vt0 + it + 1) * 128) * DIN;
#pragma unroll
            for (int s = tid; s < 2048; s += 256) {
                int r = s >> 4, kq = s & 15;
                float4 f = *(const float4*)&xb[(size_t)r * DIN + kq * 4];
                __nv_bfloat162 h0 = __floats2bfloat162_rn(f.x, f.y);
                __nv_bfloat162 h1 = __floats2bfloat162_rn(f.z, f.w);
                *(uint2*)&Xs[r * PJ_XST + kq * 4] = make_uint2(*(uint32_t*)&h0, *(uint32_t*)&h1);
            }
            __syncthreads();
        }
    }
}

// ---------------------------------------------------------------------------
// transpose (+inline rinv): adjT[j][v] = bf16(adj[v][j] * rinv[v])
//   rinv reduced per block from g_part (same order — bitwise identical);
//   blocks with blockIdx.x==0 publish g_rinv for agg epilogue.
// ---------------------------------------------------------------------------
__global__ void __launch_bounds__(256) transpose_kernel(const float* __restrict__ adj) {
    __shared__ float ts[64][65];   // ts[j][v]
    __shared__ float rs[64];
    int tid = threadIdx.x;
    int j0 = blockIdx.x * 64, v0 = blockIdx.y * 64;

#pragma unroll
    for (int p = 0; p < 4; p++) {
        int r = p * 16 + (tid >> 4);
        int c = (tid & 15) * 4;
        float4 f = *(const float4*)&adj[(size_t)(v0 + r) * V + j0 + c];
        ts[c + 0][r] = f.x;
        ts[c + 1][r] = f.y;
        ts[c + 2][r] = f.z;
        ts[c + 3][r] = f.w;
    }
    if (tid < 64) {
        float s = 0.0f;
#pragma unroll
        for (int i = 0; i < 32; i++) s += g_part[i][v0 + tid];
        float r = rsqrtf(s);
        rs[tid] = r;
        if (blockIdx.x == 0) g_rinv[v0 + tid] = r;
    }
    __syncthreads();

#pragma unroll
    for (int p = 0; p < 2; p++) {
        int jr = p * 32 + (tid >> 3);
        int vo = (tid & 7) * 8;
        __nv_bfloat16 h[8];
#pragma unroll
        for (int i = 0; i < 8; i++)
            h[i] = __float2bfloat16_rn(ts[jr][vo + i] * rs[vo + i]);
        *(uint4*)&g_adjT[(size_t)(j0 + jr) * V + v0 + vo] = *(uint4*)h;
    }
}

// ---------------------------------------------------------------------------
// agg: mma.sync bf16 GEMM, CTA 128x128, 8 warps (warp 64x32), OCCUPANCY 2
// KC=64, 3-stage cp.async pipeline, one __syncthreads per chunk
// ---------------------------------------------------------------------------
#define MT 128
#define NT 128
#define KC 64
#define NCHUNK (V / KC)               // 32
#define LDS_STRIDE 72                 // halves per row (144 B, ldmatrix bank-free)
#define A_HALVES (MT * LDS_STRIDE)    // 9216
#define B_HALVES (NT * LDS_STRIDE)    // 9216
#define ST_HALVES (A_HALVES + B_HALVES)
#define SM_BYTES (3 * ST_HALVES * 2)  // 110592 B -> 2 CTAs/SM = 216 KB

__device__ __forceinline__ void load_chunk(uint32_t smem_base, int stage,
                                           int j0, int n0, int k0, int tid) {
    uint32_t sa = smem_base + (uint32_t)stage * ((uint32_t)ST_HALVES * 2u);
    uint32_t sb = sa + (uint32_t)A_HALVES * 2u;
#pragma unroll
    for (int q = 0; q < 4; q++) {
        int s = tid + q * 256;
        int r = s >> 3, o = s & 7;
        uint32_t dst = sa + (uint32_t)(r * LDS_STRIDE + o * 8) * 2u;
        CP_ASYNC16(dst, &g_adjT[(size_t)(j0 + r) * V + k0 + o * 8]);
    }
#pragma unroll
    for (int q = 0; q < 4; q++) {
        int s = tid + q * 256;
        int r = s >> 3, o = s & 7;
        uint32_t dst = sb + (uint32_t)(r * LDS_STRIDE + o * 8) * 2u;
        CP_ASYNC16(dst, &g_xT[(size_t)(n0 + r) * V + k0 + o * 8]);
    }
}

__global__ void __launch_bounds__(256, 2) agg_mma_kernel(const float* __restrict__ bias,
                                                         float* __restrict__ out) {
    extern __shared__ __align__(16) __nv_bfloat16 smem[];
    uint32_t smem_base = smem_u32(smem);
    int tid  = threadIdx.x;
    int wid  = tid >> 5, lane = tid & 31;
    int j0   = blockIdx.x * MT;
    int n0   = blockIdx.y * NT;
    int m0w  = (wid & 1) * 64;
    int n0w  = (wid >> 1) * 32;
    int lg   = lane >> 2, lc = lane & 3;

    int r_a   = lane & 15;
    int ka    = (lane >> 4) * 8;
    int n_off = (lane & 7) + ((lane >> 4) & 1) * 8;
    int k_off = ((lane >> 3) & 1) * 8;

    float d[4][4][4];
#pragma unroll
    for (int i = 0; i < 4; i++)
#pragma unroll
        for (int j = 0; j < 4; j++)
#pragma unroll
            for (int q = 0; q < 4; q++) d[i][j][q] = 0.0f;

    load_chunk(smem_base, 0, j0, n0, 0, tid);   CP_COMMIT();
    load_chunk(smem_base, 1, j0, n0, KC, tid);  CP_COMMIT();

    for (int i = 0; i < NCHUNK; i++) {
        if (i < NCHUNK - 1) { CP_WAIT(1); } else { CP_WAIT(0); }
        __syncthreads();   // chunk i resident; releases stage (i-1)%3

        int stage = i % 3;
        uint32_t As = smem_base + (uint32_t)stage * ((uint32_t)ST_HALVES * 2u);
        uint32_t Bs = As + (uint32_t)A_HALVES * 2u;
        uint32_t a_base = As + (uint32_t)((m0w + r_a) * LDS_STRIDE + ka) * 2u;
        uint32_t b_base = Bs + (uint32_t)((n0w + n_off) * LDS_STRIDE + k_off) * 2u;

#pragma unroll
        for (int k16 = 0; k16 < 4; k16++) {
            uint32_t kb2 = (uint32_t)(k16 * 16 * 2);
            uint32_t a[4][4], b[4][2];
#pragma unroll
            for (int fi = 0; fi < 4; fi++) {
                LDMATRIX_X4(a[fi][0], a[fi][1], a[fi][2], a[fi][3],
                            a_base + (uint32_t)(fi * 16 * LDS_STRIDE * 2) + kb2);
            }
#pragma unroll
            for (int p = 0; p < 2; p++) {
                LDMATRIX_X4(b[2 * p][0], b[2 * p][1], b[2 * p + 1][0], b[2 * p + 1][1],
                            b_base + (uint32_t)(p * 16 * LDS_STRIDE * 2) + kb2);
            }
#pragma unroll
            for (int fi = 0; fi < 4; fi++)
#pragma unroll
                for (int fj = 0; fj < 4; fj++)
                    mma_bf16(d[fi][fj], a[fi], b[fj]);
        }
        if (i + 2 < NCHUNK) {
            load_chunk(smem_base, (i + 2) % 3, j0, n0, (i + 2) * KC, tid);
            CP_COMMIT();
        }
    }

    // epilogue
#pragma unroll
    for (int fi = 0; fi < 4; fi++) {
        int row_lo = j0 + m0w + fi * 16 + lg;
        int row_hi = row_lo + 8;
        float rlo = g_rinv[row_lo];
        float rhi = g_rinv[row_hi];
#pragma unroll
        for (int fj = 0; fj < 4; fj++) {
            int c  = n0 + n0w + fj * 8 + lc * 2;
            int ab = c >> 6;
            int dd = c & 63;
            float2 bi = *(const float2*)&bias[dd];
            float2 olo, ohi;
            olo.x = fmaxf(bi.x + rlo * d[fi][fj][0], 0.0f);
            olo.y = fmaxf(bi.y + rlo * d[fi][fj][1], 0.0f);
            ohi.x = fmaxf(bi.x + rhi * d[fi][fj][2], 0.0f);
            ohi.y = fmaxf(bi.y + rhi * d[fi][fj][3], 0.0f);
            *(float2*)&out[((size_t)ab * V + row_lo) * DOUT + dd] = olo;
            *(float2*)&out[((size_t)ab * V + row_hi) * DOUT + dd] = ohi;
        }
    }
}

// ---------------------------------------------------------------------------
extern "C" void kernel_launch(void* const* d_in, const int* in_sizes, int n_in,
                              void* d_out, int out_size) {
    const float* adj  = (const float*)d_in[0];
    const float* x    = (const float*)d_in[1];
    const float* w    = (const float*)d_in[2];
    const float* bias = (const float*)d_in[3];
    float* out        = (float*)d_out;

    cudaFuncSetAttribute(agg_mma_kernel, cudaFuncAttributeMaxDynamicSharedMemorySize, SM_BYTES);

    fused_proj_colsum_kernel<<<512, 256>>>(x, w, adj);
    transpose_kernel<<<dim3(32, 32), 256>>>(adj);
    agg_mma_kernel<<<dim3(V / MT, NCOL / NT), 256, SM_BYTES>>>(bias, out);
}

// round 16
// speedup vs baseline: 1.0303x; 1.0169x over previous
#include <cuda_runtime.h>
#include <cuda_bf16.h>
#include <cstdint>

#define V     2048
#define DIN   64
#define DOUT  64
#define NB    64            // A*B = 8*8
#define NCOL  (NB * DOUT)   // 4096 columns of the big GEMM

// ---------------- scratch (device globals; no cudaMalloc allowed) ----------
__device__ __nv_bfloat16 g_adjT[(size_t)V * V];   // 8 MB: adjT[j][v] = bf16(adj[v][j]*rinv[v])
__device__ __nv_bfloat16 g_xT[(size_t)NCOL * V];  // 16 MB: xT[c][v] = bf16((x@W)[ab,v,d])
__device__ float g_part[32][V];                   // colsum partials (overwritten fully each run)
__device__ float g_rinv[V];

// ---------------- helpers ---------------------------------------------------
__device__ __forceinline__ uint32_t smem_u32(const void* p) {
    uint32_t a;
    asm("{ .reg .u64 t; cvta.to.shared.u64 t, %1; cvt.u32.u64 %0, t; }" : "=r"(a) : "l"(p));
    return a;
}
#define CP_ASYNC16(dst, src) \
    asm volatile("cp.async.cg.shared.global [%0], [%1], 16;" :: "r"(dst), "l"(src) : "memory")
#define CP_COMMIT() asm volatile("cp.async.commit_group;" ::: "memory")
#define CP_WAIT(n)  asm volatile("cp.async.wait_group %0;" :: "n"(n) : "memory")

// m16n8k16 bf16 mma: D += A*B, fp32 accum
__device__ __forceinline__ void mma_bf16(float* d, const uint32_t* a, const uint32_t* b) {
    asm volatile(
        "mma.sync.aligned.m16n8k16.row.col.f32.bf16.bf16.f32 "
        "{%0,%1,%2,%3}, {%4,%5,%6,%7}, {%8,%9}, {%0,%1,%2,%3};"
        : "+f"(d[0]), "+f"(d[1]), "+f"(d[2]), "+f"(d[3])
        : "r"(a[0]), "r"(a[1]), "r"(a[2]), "r"(a[3]), "r"(b[0]), "r"(b[1]));
}
#define LDMATRIX_X4(r0, r1, r2, r3, addr) \
    asm volatile("ldmatrix.sync.aligned.m8n8.x4.shared.b16 {%0,%1,%2,%3}, [%4];" \
        : "=r"(r0), "=r"(r1), "=r"(r2), "=r"(r3) : "r"(addr))

// ---------------------------------------------------------------------------
// Fused launch 1 (SINGLE WAVE): blocks [0,256) = project (4 v-tiles each),
// blocks [256,512) = colsum. 512 blocks, occ>=4 -> one wave + in-SM overlap.
// b-frags prebuilt PER TILE inside the loop (folded LDS, ~56 regs — R12
// shape), NOT hoisted across tiles (R14's 128-reg mistake).
// ---------------------------------------------------------------------------
#define PJ_WTST  72                  // Wth row stride (halves)
#define PJ_XST   72                  // Xs row stride (halves)
#define PJ_YST   136                 // Ys row stride (halves)
#define PJ_WT_BYTES (DOUT * PJ_WTST * 2)       // 9216
#define PJ_XS_BYTES (128 * PJ_XST * 2)         // 18432 (Ys needs 64*136*2=17408 <=)

__global__ void __launch_bounds__(256) fused_proj_colsum_kernel(
        const float* __restrict__ x, const float* __restrict__ w,
        const float* __restrict__ adj) {
    __shared__ __align__(16) char smem_raw[PJ_WT_BYTES + PJ_XS_BYTES];

    int tid = threadIdx.x;
    int b   = blockIdx.x;

    if (b >= 256) {
        // ---- colsum partials: g_part[ib][j] = sum of 64 adj rows ----
        int cb = b - 256;
        int j  = (cb & 7) * 256 + tid;
        int i0 = (cb >> 3) * 64;
        float s0 = 0.0f, s1 = 0.0f;
#pragma unroll 8
        for (int i = 0; i < 32; i++) {
            s0 += adj[(size_t)(i0 + 2 * i)     * V + j];
            s1 += adj[(size_t)(i0 + 2 * i + 1) * V + j];
        }
        g_part[cb >> 3][j] = s0 + s1;
        return;
    }

    // ---- project: 4 v-tiles of one ab per block ----
    __nv_bfloat16* Wth = (__nv_bfloat16*)smem_raw;                  // [d][k]
    __nv_bfloat16* Xs  = (__nv_bfloat16*)(smem_raw + PJ_WT_BYTES);  // [v][k]
    __nv_bfloat16* Ys  = Xs;                                        // reused per tile

    int wid  = tid >> 5, lane = tid & 31;
    int lg   = lane >> 2, lc = lane & 3;
    int ab   = b >> 2;
    int vt0  = (b & 3) * 4;          // first of 4 v-tiles

    // stage W transposed to bf16: Wth[d][k] = bf16(w[k][d])
#pragma unroll
    for (int s = tid; s < 1024; s += 256) {
        int k = s >> 4, dq = (s & 15) * 4;
        float4 f = *(const float4*)&w[k * DOUT + dq];
        Wth[(dq + 0) * PJ_WTST + k] = __float2bfloat16_rn(f.x);
        Wth[(dq + 1) * PJ_WTST + k] = __float2bfloat16_rn(f.y);
        Wth[(dq + 2) * PJ_WTST + k] = __float2bfloat16_rn(f.z);
        Wth[(dq + 3) * PJ_WTST + k] = __float2bfloat16_rn(f.w);
    }
    // stage x for tile 0
    {
        const float* xb = x + ((size_t)ab * V + vt0 * 128) * DIN;
#pragma unroll
        for (int s = tid; s < 2048; s += 256) {
            int r = s >> 4, kq = s & 15;
            float4 f = *(const float4*)&xb[(size_t)r * DIN + kq * 4];
            __nv_bfloat162 h0 = __floats2bfloat162_rn(f.x, f.y);
            __nv_bfloat162 h1 = __floats2bfloat162_rn(f.z, f.w);
            *(uint2*)&Xs[r * PJ_XST + kq * 4] = make_uint2(*(uint32_t*)&h0, *(uint32_t*)&h1);
        }
    }
    __syncthreads();

    uint32_t xs_base = smem_u32(Xs);
    int r_a = lane & 15, ka = (lane >> 4) * 8;
    uint32_t a_addr0 = xs_base + (uint32_t)((wid * 16 + r_a) * PJ_XST + ka) * 2u;

#pragma unroll 1
    for (int it = 0; it < 4; it++) {
        int v0 = (vt0 + it) * 128;

        // b-frags rebuilt per tile (folded LDS -> low live-reg count)
        uint32_t bfr[4][8][2];
#pragma unroll
        for (int k16 = 0; k16 < 4; k16++) {
#pragma unroll
            for (int fj = 0; fj < 8; fj++) {
                int n  = fj * 8 + lg;
                int k0 = k16 * 16 + lc * 2;
                bfr[k16][fj][0] = *(const uint32_t*)&Wth[n * PJ_WTST + k0];
                bfr[k16][fj][1] = *(const uint32_t*)&Wth[n * PJ_WTST + k0 + 8];
            }
        }

        float d[8][4];
#pragma unroll
        for (int j = 0; j < 8; j++)
#pragma unroll
            for (int q = 0; q < 4; q++) d[j][q] = 0.0f;

#pragma unroll
        for (int k16 = 0; k16 < 4; k16++) {
            uint32_t a[4];
            LDMATRIX_X4(a[0], a[1], a[2], a[3], a_addr0 + (uint32_t)(k16 * 16 * 2));
#pragma unroll
            for (int fj = 0; fj < 8; fj++) mma_bf16(d[fj], a, bfr[k16][fj]);
        }
        __syncthreads();   // all Xs reads done; reuse as Ys

#pragma unroll
        for (int fj = 0; fj < 8; fj++) {
            int n    = fj * 8 + lc * 2;
            int vlo  = wid * 16 + lg;
            int vhi  = vlo + 8;
            Ys[n * PJ_YST + vlo]       = __float2bfloat16_rn(d[fj][0]);
            Ys[(n + 1) * PJ_YST + vlo] = __float2bfloat16_rn(d[fj][1]);
            Ys[n * PJ_YST + vhi]       = __float2bfloat16_rn(d[fj][2]);
            Ys[(n + 1) * PJ_YST + vhi] = __float2bfloat16_rn(d[fj][3]);
        }
        __syncthreads();

#pragma unroll
        for (int s = tid; s < 1024; s += 256) {
            int n = s >> 4, vq = s & 15;
            uint4 val = *(uint4*)&Ys[n * PJ_YST + vq * 8];
            *(uint4*)&g_xT[(size_t)(ab * 64 + n) * V + v0 + vq * 8] = val;
        }

        if (it < 3) {
            __syncthreads();   // Ys reads done before restaging Xs
            const float* xb = x + ((size_t)ab * V + (vt0 + it + 1) * 128) * DIN;
#pragma unroll
            for (int s = tid; s < 2048; s += 256) {
                int r = s >> 4, kq = s & 15;
                float4 f = *(const float4*)&xb[(size_t)r * DIN + kq * 4];
                __nv_bfloat162 h0 = __floats2bfloat162_rn(f.x, f.y);
                __nv_bfloat162 h1 = __floats2bfloat162_rn(f.z, f.w);
                *(uint2*)&Xs[r * PJ_XST + kq * 4] = make_uint2(*(uint32_t*)&h0, *(uint32_t*)&h1);
            }
            __syncthreads();
        }
    }
}

// ---------------------------------------------------------------------------
// transpose (+inline rinv): adjT[j][v] = bf16(adj[v][j] * rinv[v])
//   rinv reduced per block from g_part (same order — bitwise identical);
//   blocks with blockIdx.x==0 publish g_rinv for agg epilogue.
// ---------------------------------------------------------------------------
__global__ void __launch_bounds__(256) transpose_kernel(const float* __restrict__ adj) {
    __shared__ float ts[64][65];   // ts[j][v]
    __shared__ float rs[64];
    int tid = threadIdx.x;
    int j0 = blockIdx.x * 64, v0 = blockIdx.y * 64;

#pragma unroll
    for (int p = 0; p < 4; p++) {
        int r = p * 16 + (tid >> 4);
        int c = (tid & 15) * 4;
        float4 f = *(const float4*)&adj[(size_t)(v0 + r) * V + j0 + c];
        ts[c + 0][r] = f.x;
        ts[c + 1][r] = f.y;
        ts[c + 2][r] = f.z;
        ts[c + 3][r] = f.w;
    }
    if (tid < 64) {
        float s = 0.0f;
#pragma unroll
        for (int i = 0; i < 32; i++) s += g_part[i][v0 + tid];
        float r = rsqrtf(s);
        rs[tid] = r;
        if (blockIdx.x == 0) g_rinv[v0 + tid] = r;
    }
    __syncthreads();

#pragma unroll
    for (int p = 0; p < 2; p++) {
        int jr = p * 32 + (tid >> 3);
        int vo = (tid & 7) * 8;
        __nv_bfloat16 h[8];
#pragma unroll
        for (int i = 0; i < 8; i++)
            h[i] = __float2bfloat16_rn(ts[jr][vo + i] * rs[vo + i]);
        *(uint4*)&g_adjT[(size_t)(j0 + jr) * V + v0 + vo] = *(uint4*)h;
    }
}

// ---------------------------------------------------------------------------
// agg: mma.sync bf16 GEMM, CTA 128x128, 8 warps (warp 64x32), OCCUPANCY 2
// KC=64, 3-stage cp.async pipeline, one __syncthreads per chunk
// ---------------------------------------------------------------------------
#define MT 128
#define NT 128
#define KC 64
#define NCHUNK (V / KC)               // 32
#define LDS_STRIDE 72                 // halves per row (144 B, ldmatrix bank-free)
#define A_HALVES (MT * LDS_STRIDE)    // 9216
#define B_HALVES (NT * LDS_STRIDE)    // 9216
#define ST_HALVES (A_HALVES + B_HALVES)
#define SM_BYTES (3 * ST_HALVES * 2)  // 110592 B -> 2 CTAs/SM = 216 KB

__device__ __forceinline__ void load_chunk(uint32_t smem_base, int stage,
                                           int j0, int n0, int k0, int tid) {
    uint32_t sa = smem_base + (uint32_t)stage * ((uint32_t)ST_HALVES * 2u);
    uint32_t sb = sa + (uint32_t)A_HALVES * 2u;
#pragma unroll
    for (int q = 0; q < 4; q++) {
        int s = tid + q * 256;
        int r = s >> 3, o = s & 7;
        uint32_t dst = sa + (uint32_t)(r * LDS_STRIDE + o * 8) * 2u;
        CP_ASYNC16(dst, &g_adjT[(size_t)(j0 + r) * V + k0 + o * 8]);
    }
#pragma unroll
    for (int q = 0; q < 4; q++) {
        int s = tid + q * 256;
        int r = s >> 3, o = s & 7;
        uint32_t dst = sb + (uint32_t)(r * LDS_STRIDE + o * 8) * 2u;
        CP_ASYNC16(dst, &g_xT[(size_t)(n0 + r) * V + k0 + o * 8]);
    }
}

__global__ void __launch_bounds__(256, 2) agg_mma_kernel(const float* __restrict__ bias,
                                                         float* __restrict__ out) {
    extern __shared__ __align__(16) __nv_bfloat16 smem[];
    uint32_t smem_base = smem_u32(smem);
    int tid  = threadIdx.x;
    int wid  = tid >> 5, lane = tid & 31;
    int j0   = blockIdx.x * MT;
    int n0   = blockIdx.y * NT;
    int m0w  = (wid & 1) * 64;
    int n0w  = (wid >> 1) * 32;
    int lg   = lane >> 2, lc = lane & 3;

    int r_a   = lane & 15;
    int ka    = (lane >> 4) * 8;
    int n_off = (lane & 7) + ((lane >> 4) & 1) * 8;
    int k_off = ((lane >> 3) & 1) * 8;

    float d[4][4][4];
#pragma unroll
    for (int i = 0; i < 4; i++)
#pragma unroll
        for (int j = 0; j < 4; j++)
#pragma unroll
            for (int q = 0; q < 4; q++) d[i][j][q] = 0.0f;

    load_chunk(smem_base, 0, j0, n0, 0, tid);   CP_COMMIT();
    load_chunk(smem_base, 1, j0, n0, KC, tid);  CP_COMMIT();

    for (int i = 0; i < NCHUNK; i++) {
        if (i < NCHUNK - 1) { CP_WAIT(1); } else { CP_WAIT(0); }
        __syncthreads();   // chunk i resident; releases stage (i-1)%3

        int stage = i % 3;
        uint32_t As = smem_base + (uint32_t)stage * ((uint32_t)ST_HALVES * 2u);
        uint32_t Bs = As + (uint32_t)A_HALVES * 2u;
        uint32_t a_base = As + (uint32_t)((m0w + r_a) * LDS_STRIDE + ka) * 2u;
        uint32_t b_base = Bs + (uint32_t)((n0w + n_off) * LDS_STRIDE + k_off) * 2u;

#pragma unroll
        for (int k16 = 0; k16 < 4; k16++) {
            uint32_t kb2 = (uint32_t)(k16 * 16 * 2);
            uint32_t a[4][4], b[4][2];
#pragma unroll
            for (int fi = 0; fi < 4; fi++) {
                LDMATRIX_X4(a[fi][0], a[fi][1], a[fi][2], a[fi][3],
                            a_base + (uint32_t)(fi * 16 * LDS_STRIDE * 2) + kb2);
            }
#pragma unroll
            for (int p = 0; p < 2; p++) {
                LDMATRIX_X4(b[2 * p][0], b[2 * p][1], b[2 * p + 1][0], b[2 * p + 1][1],
                            b_base + (uint32_t)(p * 16 * LDS_STRIDE * 2) + kb2);
            }
#pragma unroll
            for (int fi = 0; fi < 4; fi++)
#pragma unroll
                for (int fj = 0; fj < 4; fj++)
                    mma_bf16(d[fi][fj], a[fi], b[fj]);
        }
        if (i + 2 < NCHUNK) {
            load_chunk(smem_base, (i + 2) % 3, j0, n0, (i + 2) * KC, tid);
            CP_COMMIT();
        }
    }

    // epilogue
#pragma unroll
    for (int fi = 0; fi < 4; fi++) {
        int row_lo = j0 + m0w + fi * 16 + lg;
        int row_hi = row_lo + 8;
        float rlo = g_rinv[row_lo];
        float rhi = g_rinv[row_hi];
#pragma unroll
        for (int fj = 0; fj < 4; fj++) {
            int c  = n0 + n0w + fj * 8 + lc * 2;
            int ab = c >> 6;
            int dd = c & 63;
            float2 bi = *(const float2*)&bias[dd];
            float2 olo, ohi;
            olo.x = fmaxf(bi.x + rlo * d[fi][fj][0], 0.0f);
            olo.y = fmaxf(bi.y + rlo * d[fi][fj][1], 0.0f);
            ohi.x = fmaxf(bi.x + rhi * d[fi][fj][2], 0.0f);
            ohi.y = fmaxf(bi.y + rhi * d[fi][fj][3], 0.0f);
            *(float2*)&out[((size_t)ab * V + row_lo) * DOUT + dd] = olo;
            *(float2*)&out[((size_t)ab * V + row_hi) * DOUT + dd] = ohi;
        }
    }
}

// ---------------------------------------------------------------------------
extern "C" void kernel_launch(void* const* d_in, const int* in_sizes, int n_in,
                              void* d_out, int out_size) {
    const float* adj  = (const float*)d_in[0];
    const float* x    = (const float*)d_in[1];
    const float* w    = (const float*)d_in[2];
    const float* bias = (const float*)d_in[3];
    float* out        = (float*)d_out;

    cudaFuncSetAttribute(agg_mma_kernel, cudaFuncAttributeMaxDynamicSharedMemorySize, SM_BYTES);

    fused_proj_colsum_kernel<<<512, 256>>>(x, w, adj);
    transpose_kernel<<<dim3(32, 32), 256>>>(adj);
    agg_mma_kernel<<<dim3(V / MT, NCOL / NT), 256, SM_BYTES>>>(bias, out);
}